// round 6
// baseline (speedup 1.0000x reference)
#include <cuda_runtime.h>

#define ND 32
#define NB 128
#define N0N1 16384
#define MAIN_CTAS 256
#define PPC (N0N1 / MAIN_CTAS)   /* 64 pairs per CTA */
#define PSTRIDE 68               /* floats per partial record (17 float4) */

__device__ float4 g_part4[MAIN_CTAS * NB * (PSTRIDE/4)];

typedef unsigned long long u64;

// ---- packed f32x2 helpers (sm_100+) --------------------------------------
__device__ __forceinline__ u64 pk2(float lo, float hi) {
    u64 r; asm("mov.b64 %0,{%1,%2};" : "=l"(r) : "f"(lo), "f"(hi)); return r;
}
__device__ __forceinline__ u64 fma2(u64 a, u64 b, u64 c) {
    u64 d; asm("fma.rn.f32x2 %0,%1,%2,%3;" : "=l"(d) : "l"(a), "l"(b), "l"(c)); return d;
}
__device__ __forceinline__ u64 add2(u64 a, u64 b) {
    u64 d; asm("add.rn.f32x2 %0,%1,%2;" : "=l"(d) : "l"(a), "l"(b)); return d;
}
__device__ __forceinline__ float2 upk(u64 a) {
    float lo, hi; asm("mov.b64 {%0,%1},%2;" : "=f"(lo), "=f"(hi) : "l"(a));
    return make_float2(lo, hi);
}

// ---- per-dim geometry ----------------------------------------------------
struct Geo { float nh, P, K, G, cl; };
__device__ __forceinline__ Geo geo(float s0, float s1, float m0, float m1,
                                   float t, float u) {
    const float eps2 = 0.25f, eps4 = 0.0625f;
    float Ds    = sqrtf(fmaf(4.0f*s0, s1, eps4));
    float Cs    = 0.5f*(Ds - eps2);
    float Sigma = u*u*s0 + t*t*s1 + 2.0f*t*u*Cs + eps2*t*u;
    float St    = (t*s1 + u*Cs) - (u*s0 + t*Cs) - eps2*t;
    float rS    = __fdividef(1.0f, Sigma);
    float mut   = u*m0 + t*m1;
    Geo g;
    g.K  = St * rS;
    g.nh = -0.5f * rS;
    g.P  = rS * mut;
    g.G  = g.K*mut - (m1 - m0);
    g.cl = fmaf(g.nh, mut*mut, -0.5f*__logf(Sigma));
    return g;
}

// ---------------------------------------------------------------------------
// Fused kernel: prologue computes this CTA's 64 pairs' packs into smem,
// main loop: thread = (batch b, half h), 16 dims each, f32x2 packed math.
// smem per pair: 16 ulonglong2, index = (gg&7)*2 + (gg>>3)  [gg = dim-pair]
//   s1 entry = (nh01, P01), s2 entry = (K01, G01).
// ---------------------------------------------------------------------------
__global__ void __launch_bounds__(256) gmm_main(
    const float* __restrict__ X,   const float* __restrict__ t_in,
    const float* __restrict__ Mu0, const float* __restrict__ Mu1,
    const float* __restrict__ S0,  const float* __restrict__ S1,
    const float* __restrict__ Lam)
{
    __shared__ ulonglong2 s1[PPC*16];
    __shared__ ulonglong2 s2[PPC*16];
    __shared__ float sc[PPC];
    __shared__ float slam[PPC];

    int tid = threadIdx.x;

    // ------- prologue: 4 threads per pair, 8 dims (2 quads) each ---------
    {
        int pl = tid >> 2, qq = tid & 3;              // pair-local, dim-octet
        int pair = blockIdx.x * PPC + pl;
        int i = pair >> 7, j = pair & 127;
        float t = t_in[0], u = 1.0f - t;

        Geo g[8];
        #pragma unroll
        for (int half = 0; half < 2; half++) {
            int d0 = qq*8 + half*4;
            float4 s0v = *(const float4*)(S0  + i*ND + d0);
            float4 s1v = *(const float4*)(S1  + j*ND + d0);
            float4 m0v = *(const float4*)(Mu0 + i*ND + d0);
            float4 m1v = *(const float4*)(Mu1 + j*ND + d0);
            g[half*4+0] = geo(s0v.x, s1v.x, m0v.x, m1v.x, t, u);
            g[half*4+1] = geo(s0v.y, s1v.y, m0v.y, m1v.y, t, u);
            g[half*4+2] = geo(s0v.z, s1v.z, m0v.z, m1v.z, t, u);
            g[half*4+3] = geo(s0v.w, s1v.w, m0v.w, m1v.w, t, u);
        }

        #pragma unroll
        for (int e = 0; e < 4; e++) {                 // dim-pairs gg = 4*qq+e
            int gg = 4*qq + e;
            int idx = pl*16 + (gg & 7)*2 + (gg >> 3);
            Geo a = g[2*e], bb = g[2*e+1];
            s1[idx] = make_ulonglong2(pk2(a.nh, bb.nh), pk2(a.P, bb.P));
            s2[idx] = make_ulonglong2(pk2(a.K,  bb.K ), pk2(a.G, bb.G));
        }

        float cl = ((g[0].cl + g[1].cl) + (g[2].cl + g[3].cl))
                 + ((g[4].cl + g[5].cl) + (g[6].cl + g[7].cl));
        cl += __shfl_xor_sync(0xffffffffu, cl, 1);
        cl += __shfl_xor_sync(0xffffffffu, cl, 2);
        if (qq == 0) { sc[pl] = cl; slam[pl] = Lam[pair]; }
    }

    // ------- main loop: thread = (b, half) -------------------------------
    int b = tid >> 1, h = tid & 1;

    u64 x2[8];
    {
        const ulonglong2* Xv = (const ulonglong2*)(X + b*ND + h*16);
        #pragma unroll
        for (int g = 0; g < 4; g++) {
            ulonglong2 xx = Xv[g];
            x2[2*g] = xx.x; x2[2*g+1] = xx.y;
        }
    }
    u64 aK2[8], aG2[8];
    #pragma unroll
    for (int g = 0; g < 8; g++) { aK2[g] = 0ull; aG2[g] = 0ull; }
    float den = 0.f;

    __syncthreads();

    #pragma unroll 2
    for (int p = 0; p < PPC; p++) {
        const ulonglong2* q1 = s1 + p*16 + h;
        u64 c0 = 0ull, c1 = 0ull;
        #pragma unroll
        for (int g = 0; g < 8; g++) {
            ulonglong2 a = q1[g*2];
            u64 tmp = fma2(a.x, x2[g], a.y);          // nh*x + P
            if (g & 1) c1 = fma2(tmp, x2[g], c1);     // (nh*x + P)*x
            else       c0 = fma2(tmp, x2[g], c0);
        }
        float2 cf = upk(add2(c0, c1));
        float lwh = cf.x + cf.y;
        float lws = lwh + __shfl_xor_sync(0xffffffffu, lwh, 1) + sc[p];
        float w = __expf(fminf(fmaxf(lws, -50.f), 50.f)) * slam[p];
        den += w;
        u64 w2 = pk2(w, w);
        const ulonglong2* q2 = s2 + p*16 + h;
        #pragma unroll
        for (int g = 0; g < 8; g++) {
            ulonglong2 kg = q2[g*2];
            aK2[g] = fma2(w2, kg.x, aK2[g]);
            aG2[g] = fma2(w2, kg.y, aG2[g]);
        }
    }

    float* pp = (float*)g_part4 + (size_t)(blockIdx.x*NB + b)*PSTRIDE;
    ulonglong2* pv = (ulonglong2*)pp;
    #pragma unroll
    for (int g = 0; g < 4; g++)
        pv[h*4 + g] = make_ulonglong2(aK2[2*g], aK2[2*g+1]);
    #pragma unroll
    for (int g = 0; g < 4; g++)
        pv[8 + h*4 + g] = make_ulonglong2(aG2[2*g], aG2[2*g+1]);
    if (h == 0) pp[64] = den;
}

// ---------------------------------------------------------------------------
// Reduce: block = b, 1024 threads = 32 groups x 32 lanes; each group
// fully-unrolled over its 8 records (MAIN_CTAS/32) -> deep MLP.
// ---------------------------------------------------------------------------
__global__ void __launch_bounds__(1024) gmm_reduce(const float* __restrict__ X,
                                                   float* __restrict__ out) {
    __shared__ float rK[1024], rG[1024], rD[1024];
    int b = blockIdx.x;
    int tid = threadIdx.x;
    int n = tid & 31, q = tid >> 5;

    float sK = 0.f, sG = 0.f, dn = 0.f;
    const float* base = (const float*)g_part4 + (size_t)b*PSTRIDE;
    #pragma unroll
    for (int r = 0; r < MAIN_CTAS/32; r++) {
        const float* pp = base + (size_t)(q*(MAIN_CTAS/32) + r)*(NB*PSTRIDE);
        sK += pp[n];
        sG += pp[32+n];
        dn += pp[64];
    }
    rK[tid] = sK; rG[tid] = sG; rD[tid] = dn;
    __syncthreads();
    if (q == 0) {
        #pragma unroll
        for (int r = 1; r < 32; r++) {
            sK += rK[n + 32*r]; sG += rG[n + 32*r]; dn += rD[n + 32*r];
        }
        out[b*ND + n] = (X[b*ND + n]*sK - sG) / dn;
    }
}

// ---------------------------------------------------------------------------
extern "C" void kernel_launch(void* const* d_in, const int* in_sizes, int n_in,
                              void* d_out, int out_size) {
    const float* X   = (const float*)d_in[0];
    const float* t   = (const float*)d_in[1];
    const float* Mu0 = (const float*)d_in[2];
    const float* Mu1 = (const float*)d_in[3];
    const float* S0  = (const float*)d_in[4];
    const float* S1  = (const float*)d_in[5];
    const float* Lam = (const float*)d_in[6];
    float* out = (float*)d_out;

    gmm_main<<<MAIN_CTAS, 256>>>(X, t, Mu0, Mu1, S0, S1, Lam);
    gmm_reduce<<<NB, 1024>>>(X, out);
}

// round 9
// speedup vs baseline: 1.3037x; 1.3037x over previous
#include <cuda_runtime.h>

#define ND 32
#define NB 128
#define N0N1 16384
#define MAIN_CTAS 512
#define PPC (N0N1 / MAIN_CTAS)   /* 32 pairs per CTA */
#define PSTRIDE 36               /* floats per partial record: num[32], den, pad */

__device__ float4 g_part4[MAIN_CTAS * NB * (PSTRIDE/4)];

typedef unsigned long long u64;

// ---- packed f32x2 helpers (sm_100+) --------------------------------------
__device__ __forceinline__ u64 pk2(float lo, float hi) {
    u64 r; asm("mov.b64 %0,{%1,%2};" : "=l"(r) : "f"(lo), "f"(hi)); return r;
}
__device__ __forceinline__ u64 fma2(u64 a, u64 b, u64 c) {
    u64 d; asm("fma.rn.f32x2 %0,%1,%2,%3;" : "=l"(d) : "l"(a), "l"(b), "l"(c)); return d;
}
__device__ __forceinline__ u64 add2(u64 a, u64 b) {
    u64 d; asm("add.rn.f32x2 %0,%1,%2;" : "=l"(d) : "l"(a), "l"(b)); return d;
}
__device__ __forceinline__ float2 upk(u64 a) {
    float lo, hi; asm("mov.b64 {%0,%1},%2;" : "=f"(lo), "=f"(hi) : "l"(a));
    return make_float2(lo, hi);
}

// ---- per-dim geometry ----------------------------------------------------
// NOTE: G here is PRE-NEGATED vs earlier rounds: G' = v - K*mut, so that
// num_partial[n] = x[n]*aK[n] + aG'[n] directly.
struct Geo { float nh, P, K, G, cl; };
__device__ __forceinline__ Geo geo(float s0, float s1, float m0, float m1,
                                   float t, float u) {
    const float eps2 = 0.25f, eps4 = 0.0625f;
    float Ds    = sqrtf(fmaf(4.0f*s0, s1, eps4));
    float Cs    = 0.5f*(Ds - eps2);
    float Sigma = u*u*s0 + t*t*s1 + 2.0f*t*u*Cs + eps2*t*u;
    float St    = (t*s1 + u*Cs) - (u*s0 + t*Cs) - eps2*t;
    float rS    = __fdividef(1.0f, Sigma);
    float mut   = u*m0 + t*m1;
    Geo g;
    g.K  = St * rS;
    g.nh = -0.5f * rS;
    g.P  = rS * mut;
    g.G  = fmaf(-g.K, mut, m1 - m0);                 // v - K*mut
    g.cl = fmaf(g.nh, mut*mut, -0.5f*__logf(Sigma));
    return g;
}

// ---- empty pad kernels: shift ncu -s5 capture onto gmm_main ---------------
__global__ void k_pad0() {}
__global__ void k_pad1() {}

// ---------------------------------------------------------------------------
// Fused kernel (R3-measured config): prologue computes this CTA's 32 pairs'
// packs into smem, main loop: thread = (batch b, half h), f32x2 packed math.
// ---------------------------------------------------------------------------
__global__ void __launch_bounds__(256) gmm_main(
    const float* __restrict__ X,   const float* __restrict__ t_in,
    const float* __restrict__ Mu0, const float* __restrict__ Mu1,
    const float* __restrict__ S0,  const float* __restrict__ S1,
    const float* __restrict__ Lam)
{
    __shared__ ulonglong2 s1[PPC*16];
    __shared__ ulonglong2 s2[PPC*16];
    __shared__ float sc[PPC];
    __shared__ float slam[PPC];

    int tid = threadIdx.x;

    // ---------------- prologue: 8 threads per pair, 4 dims each ----------
    {
        int pl = tid >> 3, q = tid & 7;               // pair-local, dim quad
        int pair = blockIdx.x * PPC + pl;
        int i = pair >> 7, j = pair & 127;
        float t = t_in[0], u = 1.0f - t;

        float4 s0v = *(const float4*)(S0  + i*ND + q*4);
        float4 s1v = *(const float4*)(S1  + j*ND + q*4);
        float4 m0v = *(const float4*)(Mu0 + i*ND + q*4);
        float4 m1v = *(const float4*)(Mu1 + j*ND + q*4);

        Geo g0 = geo(s0v.x, s1v.x, m0v.x, m1v.x, t, u);
        Geo g1 = geo(s0v.y, s1v.y, m0v.y, m1v.y, t, u);
        Geo g2 = geo(s0v.z, s1v.z, m0v.z, m1v.z, t, u);
        Geo g3 = geo(s0v.w, s1v.w, m0v.w, m1v.w, t, u);

        int ggA = 2*q, ggB = 2*q + 1;                 // global dim-pairs
        int iA = pl*16 + (ggA & 7)*2 + (ggA >> 3);
        int iB = pl*16 + (ggB & 7)*2 + (ggB >> 3);
        s1[iA] = make_ulonglong2(pk2(g0.nh, g1.nh), pk2(g0.P, g1.P));
        s2[iA] = make_ulonglong2(pk2(g0.K,  g1.K ), pk2(g0.G, g1.G));
        s1[iB] = make_ulonglong2(pk2(g2.nh, g3.nh), pk2(g2.P, g3.P));
        s2[iB] = make_ulonglong2(pk2(g2.K,  g3.K ), pk2(g2.G, g3.G));

        float cl = ((g0.cl + g1.cl) + (g2.cl + g3.cl));
        cl += __shfl_xor_sync(0xffffffffu, cl, 1);
        cl += __shfl_xor_sync(0xffffffffu, cl, 2);
        cl += __shfl_xor_sync(0xffffffffu, cl, 4);
        if (q == 0) { sc[pl] = cl; slam[pl] = Lam[pair]; }
    }

    // ---------------- main loop: thread = (b, half) -----------------------
    int b = tid >> 1, h = tid & 1;

    u64 x2[8];
    {
        const ulonglong2* Xv = (const ulonglong2*)(X + b*ND + h*16);
        #pragma unroll
        for (int g = 0; g < 4; g++) {
            ulonglong2 xx = Xv[g];
            x2[2*g] = xx.x; x2[2*g+1] = xx.y;
        }
    }
    u64 aK2[8], aG2[8];
    #pragma unroll
    for (int g = 0; g < 8; g++) { aK2[g] = 0ull; aG2[g] = 0ull; }
    float den = 0.f;

    __syncthreads();

    for (int p = 0; p < PPC; p++) {
        const ulonglong2* q1 = s1 + p*16 + h;
        u64 c0 = 0ull, c1 = 0ull;
        #pragma unroll
        for (int g = 0; g < 8; g++) {
            ulonglong2 a = q1[g*2];
            u64 tmp = fma2(a.x, x2[g], a.y);          // nh*x + P
            if (g & 1) c1 = fma2(tmp, x2[g], c1);     // (nh*x + P)*x
            else       c0 = fma2(tmp, x2[g], c0);
        }
        float2 cf = upk(add2(c0, c1));
        float lwh = cf.x + cf.y;
        float lws = lwh + __shfl_xor_sync(0xffffffffu, lwh, 1) + sc[p];
        float w = __expf(fminf(fmaxf(lws, -50.f), 50.f)) * slam[p];
        den += w;
        u64 w2 = pk2(w, w);
        const ulonglong2* q2 = s2 + p*16 + h;
        #pragma unroll
        for (int g = 0; g < 8; g++) {
            ulonglong2 kg = q2[g*2];
            aK2[g] = fma2(w2, kg.x, aK2[g]);
            aG2[g] = fma2(w2, kg.y, aG2[g]);          // accumulates w*(v - K*mut)
        }
    }

    // Epilogue: fold x in -> numP = x*aK + aG'
    u64 n2[8];
    #pragma unroll
    for (int g = 0; g < 8; g++) n2[g] = fma2(x2[g], aK2[g], aG2[g]);

    float* pp = (float*)g_part4 + (size_t)(blockIdx.x*NB + b)*PSTRIDE;
    ulonglong2* pv = (ulonglong2*)pp;
    #pragma unroll
    for (int g = 0; g < 4; g++)
        pv[h*4 + g] = make_ulonglong2(n2[2*g], n2[2*g+1]);
    if (h == 0) pp[32] = den;
}

// ---------------------------------------------------------------------------
// Reduce: block = b, 1024 threads = 32 groups x 32 lanes; each group
// fully-unrolled over its 16 records (MAIN_CTAS/32) -> deep MLP.
// ---------------------------------------------------------------------------
__global__ void __launch_bounds__(1024) gmm_reduce(float* __restrict__ out) {
    __shared__ float rN[1024], rD[1024];
    int b = blockIdx.x;
    int tid = threadIdx.x;
    int n = tid & 31, q = tid >> 5;

    float sN = 0.f, dn = 0.f;
    const float* base = (const float*)g_part4 + (size_t)b*PSTRIDE;
    #pragma unroll
    for (int r = 0; r < MAIN_CTAS/32; r++) {
        const float* pp = base + (size_t)(q*(MAIN_CTAS/32) + r)*(NB*PSTRIDE);
        sN += pp[n];
        dn += pp[32];
    }
    rN[tid] = sN; rD[tid] = dn;
    __syncthreads();
    if (q == 0) {
        #pragma unroll
        for (int r = 1; r < 32; r++) {
            sN += rN[n + 32*r]; dn += rD[n + 32*r];
        }
        out[b*ND + n] = sN / dn;
    }
}

// ---------------------------------------------------------------------------
extern "C" void kernel_launch(void* const* d_in, const int* in_sizes, int n_in,
                              void* d_out, int out_size) {
    const float* X   = (const float*)d_in[0];
    const float* t   = (const float*)d_in[1];
    const float* Mu0 = (const float*)d_in[2];
    const float* Mu1 = (const float*)d_in[3];
    const float* S0  = (const float*)d_in[4];
    const float* S1  = (const float*)d_in[5];
    const float* Lam = (const float*)d_in[6];
    float* out = (float*)d_out;

    // 4 launches/sequence so ncu (-s 5 -c 1) lands on gmm_main (index 5).
    k_pad0<<<1, 32>>>();
    gmm_main<<<MAIN_CTAS, 256>>>(X, t, Mu0, Mu1, S0, S1, Lam);
    gmm_reduce<<<NB, 1024>>>(out);
    k_pad1<<<1, 32>>>();
}

// round 15
// speedup vs baseline: 1.3408x; 1.0285x over previous
#include <cuda_runtime.h>

#define ND 32
#define NB 128
#define N0N1 16384
#define MAIN_CTAS 512
#define PPC (N0N1 / MAIN_CTAS)   /* 32 pairs per CTA */
#define PSTRIDE 36               /* floats per partial record: num[32], den, pad */

__device__ float4 g_part4[MAIN_CTAS * NB * (PSTRIDE/4)];

typedef unsigned long long u64;

// ---- packed f32x2 helpers (sm_100+) --------------------------------------
__device__ __forceinline__ u64 pk2(float lo, float hi) {
    u64 r; asm("mov.b64 %0,{%1,%2};" : "=l"(r) : "f"(lo), "f"(hi)); return r;
}
__device__ __forceinline__ u64 fma2(u64 a, u64 b, u64 c) {
    u64 d; asm("fma.rn.f32x2 %0,%1,%2,%3;" : "=l"(d) : "l"(a), "l"(b), "l"(c)); return d;
}
__device__ __forceinline__ u64 add2(u64 a, u64 b) {
    u64 d; asm("add.rn.f32x2 %0,%1,%2;" : "=l"(d) : "l"(a), "l"(b)); return d;
}
__device__ __forceinline__ float2 upk(u64 a) {
    float lo, hi; asm("mov.b64 {%0,%1},%2;" : "=f"(lo), "=f"(hi) : "l"(a));
    return make_float2(lo, hi);
}

// ---- per-dim geometry ----------------------------------------------------
// G is PRE-NEGATED: G' = v - K*mut, so num_partial[n] = x[n]*aK[n] + aG'[n].
struct Geo { float nh, P, K, G, cl; };
__device__ __forceinline__ Geo geo(float s0, float s1, float m0, float m1,
                                   float t, float u) {
    const float eps2 = 0.25f, eps4 = 0.0625f;
    float Ds    = sqrtf(fmaf(4.0f*s0, s1, eps4));
    float Cs    = 0.5f*(Ds - eps2);
    float Sigma = u*u*s0 + t*t*s1 + 2.0f*t*u*Cs + eps2*t*u;
    float St    = (t*s1 + u*Cs) - (u*s0 + t*Cs) - eps2*t;
    float rS    = __fdividef(1.0f, Sigma);
    float mut   = u*m0 + t*m1;
    Geo g;
    g.K  = St * rS;
    g.nh = -0.5f * rS;
    g.P  = rS * mut;
    g.G  = fmaf(-g.K, mut, m1 - m0);                 // v - K*mut
    g.cl = fmaf(g.nh, mut*mut, -0.5f*__logf(Sigma));
    return g;
}

// ---------------------------------------------------------------------------
// Fused kernel (R9-measured config, byte-identical): prologue computes this
// CTA's 32 pairs' packs into smem; main loop thread = (batch b, half h).
// ---------------------------------------------------------------------------
__global__ void __launch_bounds__(256) gmm_main(
    const float* __restrict__ X,   const float* __restrict__ t_in,
    const float* __restrict__ Mu0, const float* __restrict__ Mu1,
    const float* __restrict__ S0,  const float* __restrict__ S1,
    const float* __restrict__ Lam)
{
    __shared__ ulonglong2 s1[PPC*16];
    __shared__ ulonglong2 s2[PPC*16];
    __shared__ float sc[PPC];
    __shared__ float slam[PPC];

    int tid = threadIdx.x;

    // ---------------- prologue: 8 threads per pair, 4 dims each ----------
    {
        int pl = tid >> 3, q = tid & 7;               // pair-local, dim quad
        int pair = blockIdx.x * PPC + pl;
        int i = pair >> 7, j = pair & 127;
        float t = t_in[0], u = 1.0f - t;

        float4 s0v = *(const float4*)(S0  + i*ND + q*4);
        float4 s1v = *(const float4*)(S1  + j*ND + q*4);
        float4 m0v = *(const float4*)(Mu0 + i*ND + q*4);
        float4 m1v = *(const float4*)(Mu1 + j*ND + q*4);

        Geo g0 = geo(s0v.x, s1v.x, m0v.x, m1v.x, t, u);
        Geo g1 = geo(s0v.y, s1v.y, m0v.y, m1v.y, t, u);
        Geo g2 = geo(s0v.z, s1v.z, m0v.z, m1v.z, t, u);
        Geo g3 = geo(s0v.w, s1v.w, m0v.w, m1v.w, t, u);

        int ggA = 2*q, ggB = 2*q + 1;                 // global dim-pairs
        int iA = pl*16 + (ggA & 7)*2 + (ggA >> 3);
        int iB = pl*16 + (ggB & 7)*2 + (ggB >> 3);
        s1[iA] = make_ulonglong2(pk2(g0.nh, g1.nh), pk2(g0.P, g1.P));
        s2[iA] = make_ulonglong2(pk2(g0.K,  g1.K ), pk2(g0.G, g1.G));
        s1[iB] = make_ulonglong2(pk2(g2.nh, g3.nh), pk2(g2.P, g3.P));
        s2[iB] = make_ulonglong2(pk2(g2.K,  g3.K ), pk2(g2.G, g3.G));

        float cl = ((g0.cl + g1.cl) + (g2.cl + g3.cl));
        cl += __shfl_xor_sync(0xffffffffu, cl, 1);
        cl += __shfl_xor_sync(0xffffffffu, cl, 2);
        cl += __shfl_xor_sync(0xffffffffu, cl, 4);
        if (q == 0) { sc[pl] = cl; slam[pl] = Lam[pair]; }
    }

    // ---------------- main loop: thread = (b, half) -----------------------
    int b = tid >> 1, h = tid & 1;

    u64 x2[8];
    {
        const ulonglong2* Xv = (const ulonglong2*)(X + b*ND + h*16);
        #pragma unroll
        for (int g = 0; g < 4; g++) {
            ulonglong2 xx = Xv[g];
            x2[2*g] = xx.x; x2[2*g+1] = xx.y;
        }
    }
    u64 aK2[8], aG2[8];
    #pragma unroll
    for (int g = 0; g < 8; g++) { aK2[g] = 0ull; aG2[g] = 0ull; }
    float den = 0.f;

    __syncthreads();

    for (int p = 0; p < PPC; p++) {
        const ulonglong2* q1 = s1 + p*16 + h;
        u64 c0 = 0ull, c1 = 0ull;
        #pragma unroll
        for (int g = 0; g < 8; g++) {
            ulonglong2 a = q1[g*2];
            u64 tmp = fma2(a.x, x2[g], a.y);          // nh*x + P
            if (g & 1) c1 = fma2(tmp, x2[g], c1);     // (nh*x + P)*x
            else       c0 = fma2(tmp, x2[g], c0);
        }
        float2 cf = upk(add2(c0, c1));
        float lwh = cf.x + cf.y;
        float lws = lwh + __shfl_xor_sync(0xffffffffu, lwh, 1) + sc[p];
        float w = __expf(fminf(fmaxf(lws, -50.f), 50.f)) * slam[p];
        den += w;
        u64 w2 = pk2(w, w);
        const ulonglong2* q2 = s2 + p*16 + h;
        #pragma unroll
        for (int g = 0; g < 8; g++) {
            ulonglong2 kg = q2[g*2];
            aK2[g] = fma2(w2, kg.x, aK2[g]);
            aG2[g] = fma2(w2, kg.y, aG2[g]);          // accumulates w*(v - K*mut)
        }
    }

    // Epilogue: fold x in -> numP = x*aK + aG'
    u64 n2[8];
    #pragma unroll
    for (int g = 0; g < 8; g++) n2[g] = fma2(x2[g], aK2[g], aG2[g]);

    float* pp = (float*)g_part4 + (size_t)(blockIdx.x*NB + b)*PSTRIDE;
    ulonglong2* pv = (ulonglong2*)pp;
    #pragma unroll
    for (int g = 0; g < 4; g++)
        pv[h*4 + g] = make_ulonglong2(n2[2*g], n2[2*g+1]);
    if (h == 0) pp[32] = den;
}

// ---------------------------------------------------------------------------
// Reduce: block = b, 1024 threads = 32 groups x 32 lanes; each group
// fully-unrolled over its 16 records (MAIN_CTAS/32) -> deep MLP.
// ---------------------------------------------------------------------------
__global__ void __launch_bounds__(1024) gmm_reduce(float* __restrict__ out) {
    __shared__ float rN[1024], rD[1024];
    int b = blockIdx.x;
    int tid = threadIdx.x;
    int n = tid & 31, q = tid >> 5;

    float sN = 0.f, dn = 0.f;
    const float* base = (const float*)g_part4 + (size_t)b*PSTRIDE;
    #pragma unroll
    for (int r = 0; r < MAIN_CTAS/32; r++) {
        const float* pp = base + (size_t)(q*(MAIN_CTAS/32) + r)*(NB*PSTRIDE);
        sN += pp[n];
        dn += pp[32];
    }
    rN[tid] = sN; rD[tid] = dn;
    __syncthreads();
    if (q == 0) {
        #pragma unroll
        for (int r = 1; r < 32; r++) {
            sN += rN[n + 32*r]; dn += rD[n + 32*r];
        }
        out[b*ND + n] = sN / dn;
    }
}

// ---------------------------------------------------------------------------
extern "C" void kernel_launch(void* const* d_in, const int* in_sizes, int n_in,
                              void* d_out, int out_size) {
    const float* X   = (const float*)d_in[0];
    const float* t   = (const float*)d_in[1];
    const float* Mu0 = (const float*)d_in[2];
    const float* Mu1 = (const float*)d_in[3];
    const float* S0  = (const float*)d_in[4];
    const float* S1  = (const float*)d_in[5];
    const float* Lam = (const float*)d_in[6];
    float* out = (float*)d_out;

    // Two launches only — per-launch/graph-node overhead measured ~2-3us,
    // so every removed launch is a direct win.
    gmm_main<<<MAIN_CTAS, 256>>>(X, t, Mu0, Mu1, S0, S1, Lam);
    gmm_reduce<<<NB, 1024>>>(out);
}

// round 16
// speedup vs baseline: 1.3504x; 1.0072x over previous
#include <cuda_runtime.h>

#define ND 32
#define NB 128
#define N0N1 16384
#define MAIN_CTAS 512
#define PPC (N0N1 / MAIN_CTAS)   /* 32 pairs per CTA */
#define PSTRIDE 36               /* floats per partial record: num[32], den, pad */

__device__ float4 g_part4[MAIN_CTAS * NB * (PSTRIDE/4)];
__device__ float  g_mid[NB * 4 * 33];   /* stage-1 output: (b, quarter) x 33 */

typedef unsigned long long u64;

// ---- packed f32x2 helpers (sm_100+) --------------------------------------
__device__ __forceinline__ u64 pk2(float lo, float hi) {
    u64 r; asm("mov.b64 %0,{%1,%2};" : "=l"(r) : "f"(lo), "f"(hi)); return r;
}
__device__ __forceinline__ u64 fma2(u64 a, u64 b, u64 c) {
    u64 d; asm("fma.rn.f32x2 %0,%1,%2,%3;" : "=l"(d) : "l"(a), "l"(b), "l"(c)); return d;
}
__device__ __forceinline__ u64 add2(u64 a, u64 b) {
    u64 d; asm("add.rn.f32x2 %0,%1,%2;" : "=l"(d) : "l"(a), "l"(b)); return d;
}
__device__ __forceinline__ float2 upk(u64 a) {
    float lo, hi; asm("mov.b64 {%0,%1},%2;" : "=f"(lo), "=f"(hi) : "l"(a));
    return make_float2(lo, hi);
}

// ---- per-dim geometry ----------------------------------------------------
// G is PRE-NEGATED: G' = v - K*mut, so num_partial[n] = x[n]*aK[n] + aG'[n].
struct Geo { float nh, P, K, G, cl; };
__device__ __forceinline__ Geo geo(float s0, float s1, float m0, float m1,
                                   float t, float u) {
    const float eps2 = 0.25f, eps4 = 0.0625f;
    float Ds    = sqrtf(fmaf(4.0f*s0, s1, eps4));
    float Cs    = 0.5f*(Ds - eps2);
    float Sigma = u*u*s0 + t*t*s1 + 2.0f*t*u*Cs + eps2*t*u;
    float St    = (t*s1 + u*Cs) - (u*s0 + t*Cs) - eps2*t;
    float rS    = __fdividef(1.0f, Sigma);
    float mut   = u*m0 + t*m1;
    Geo g;
    g.K  = St * rS;
    g.nh = -0.5f * rS;
    g.P  = rS * mut;
    g.G  = fmaf(-g.K, mut, m1 - m0);                 // v - K*mut
    g.cl = fmaf(g.nh, mut*mut, -0.5f*__logf(Sigma));
    return g;
}

// ---------------------------------------------------------------------------
// Fused kernel (R9/R15-measured config, byte-identical).
// ---------------------------------------------------------------------------
__global__ void __launch_bounds__(256) gmm_main(
    const float* __restrict__ X,   const float* __restrict__ t_in,
    const float* __restrict__ Mu0, const float* __restrict__ Mu1,
    const float* __restrict__ S0,  const float* __restrict__ S1,
    const float* __restrict__ Lam)
{
    __shared__ ulonglong2 s1[PPC*16];
    __shared__ ulonglong2 s2[PPC*16];
    __shared__ float sc[PPC];
    __shared__ float slam[PPC];

    int tid = threadIdx.x;

    // ---------------- prologue: 8 threads per pair, 4 dims each ----------
    {
        int pl = tid >> 3, q = tid & 7;               // pair-local, dim quad
        int pair = blockIdx.x * PPC + pl;
        int i = pair >> 7, j = pair & 127;
        float t = t_in[0], u = 1.0f - t;

        float4 s0v = *(const float4*)(S0  + i*ND + q*4);
        float4 s1v = *(const float4*)(S1  + j*ND + q*4);
        float4 m0v = *(const float4*)(Mu0 + i*ND + q*4);
        float4 m1v = *(const float4*)(Mu1 + j*ND + q*4);

        Geo g0 = geo(s0v.x, s1v.x, m0v.x, m1v.x, t, u);
        Geo g1 = geo(s0v.y, s1v.y, m0v.y, m1v.y, t, u);
        Geo g2 = geo(s0v.z, s1v.z, m0v.z, m1v.z, t, u);
        Geo g3 = geo(s0v.w, s1v.w, m0v.w, m1v.w, t, u);

        int ggA = 2*q, ggB = 2*q + 1;                 // global dim-pairs
        int iA = pl*16 + (ggA & 7)*2 + (ggA >> 3);
        int iB = pl*16 + (ggB & 7)*2 + (ggB >> 3);
        s1[iA] = make_ulonglong2(pk2(g0.nh, g1.nh), pk2(g0.P, g1.P));
        s2[iA] = make_ulonglong2(pk2(g0.K,  g1.K ), pk2(g0.G, g1.G));
        s1[iB] = make_ulonglong2(pk2(g2.nh, g3.nh), pk2(g2.P, g3.P));
        s2[iB] = make_ulonglong2(pk2(g2.K,  g3.K ), pk2(g2.G, g3.G));

        float cl = ((g0.cl + g1.cl) + (g2.cl + g3.cl));
        cl += __shfl_xor_sync(0xffffffffu, cl, 1);
        cl += __shfl_xor_sync(0xffffffffu, cl, 2);
        cl += __shfl_xor_sync(0xffffffffu, cl, 4);
        if (q == 0) { sc[pl] = cl; slam[pl] = Lam[pair]; }
    }

    // ---------------- main loop: thread = (b, half) -----------------------
    int b = tid >> 1, h = tid & 1;

    u64 x2[8];
    {
        const ulonglong2* Xv = (const ulonglong2*)(X + b*ND + h*16);
        #pragma unroll
        for (int g = 0; g < 4; g++) {
            ulonglong2 xx = Xv[g];
            x2[2*g] = xx.x; x2[2*g+1] = xx.y;
        }
    }
    u64 aK2[8], aG2[8];
    #pragma unroll
    for (int g = 0; g < 8; g++) { aK2[g] = 0ull; aG2[g] = 0ull; }
    float den = 0.f;

    __syncthreads();

    for (int p = 0; p < PPC; p++) {
        const ulonglong2* q1 = s1 + p*16 + h;
        u64 c0 = 0ull, c1 = 0ull;
        #pragma unroll
        for (int g = 0; g < 8; g++) {
            ulonglong2 a = q1[g*2];
            u64 tmp = fma2(a.x, x2[g], a.y);          // nh*x + P
            if (g & 1) c1 = fma2(tmp, x2[g], c1);     // (nh*x + P)*x
            else       c0 = fma2(tmp, x2[g], c0);
        }
        float2 cf = upk(add2(c0, c1));
        float lwh = cf.x + cf.y;
        float lws = lwh + __shfl_xor_sync(0xffffffffu, lwh, 1) + sc[p];
        float w = __expf(fminf(fmaxf(lws, -50.f), 50.f)) * slam[p];
        den += w;
        u64 w2 = pk2(w, w);
        const ulonglong2* q2 = s2 + p*16 + h;
        #pragma unroll
        for (int g = 0; g < 8; g++) {
            ulonglong2 kg = q2[g*2];
            aK2[g] = fma2(w2, kg.x, aK2[g]);
            aG2[g] = fma2(w2, kg.y, aG2[g]);          // accumulates w*(v - K*mut)
        }
    }

    // Epilogue: fold x in -> numP = x*aK + aG'
    u64 n2[8];
    #pragma unroll
    for (int g = 0; g < 8; g++) n2[g] = fma2(x2[g], aK2[g], aG2[g]);

    float* pp = (float*)g_part4 + (size_t)(blockIdx.x*NB + b)*PSTRIDE;
    ulonglong2* pv = (ulonglong2*)pp;
    #pragma unroll
    for (int g = 0; g < 4; g++)
        pv[h*4 + g] = make_ulonglong2(n2[2*g], n2[2*g+1]);
    if (h == 0) pp[32] = den;
}

// ---------------------------------------------------------------------------
// Reduce stage 1: grid (128 b, 4 quarters) x 256. Block reduces 128 records
// (8 lane-groups x 16 records) for its b into g_mid[(b*4+s)*33 + {0..32}].
// ---------------------------------------------------------------------------
__global__ void __launch_bounds__(256) gmm_red1() {
    __shared__ float sm[8*33];
    int b = blockIdx.x, s = blockIdx.y;
    int tid = threadIdx.x, g = tid >> 5, lane = tid & 31;

    const float* base = (const float*)g_part4 + (size_t)b*PSTRIDE;
    float sN = 0.f, dn = 0.f;
    #pragma unroll
    for (int r = 0; r < 16; r++) {
        const float* pp = base + (size_t)(s*128 + g*16 + r)*(NB*PSTRIDE);
        sN += pp[lane];
        dn += pp[32];
    }
    sm[g*33 + lane] = sN;
    if (lane == 0) sm[g*33 + 32] = dn;
    __syncthreads();
    if (tid < 33) {
        float v = 0.f;
        #pragma unroll
        for (int g2 = 0; g2 < 8; g2++) v += sm[g2*33 + tid];
        g_mid[(b*4 + s)*33 + tid] = v;
    }
}

// ---------------------------------------------------------------------------
// Reduce stage 2: 128 blocks x 64 threads; combine 4 quarters + divide.
// ---------------------------------------------------------------------------
__global__ void __launch_bounds__(64) gmm_red2(float* __restrict__ out) {
    __shared__ float sm[33];
    int b = blockIdx.x, tid = threadIdx.x;
    if (tid < 33) {
        float v = 0.f;
        #pragma unroll
        for (int s = 0; s < 4; s++) v += g_mid[(b*4 + s)*33 + tid];
        sm[tid] = v;
    }
    __syncthreads();
    if (tid < 32) out[b*ND + tid] = sm[tid] / sm[32];
}

// ---------------------------------------------------------------------------
extern "C" void kernel_launch(void* const* d_in, const int* in_sizes, int n_in,
                              void* d_out, int out_size) {
    const float* X   = (const float*)d_in[0];
    const float* t   = (const float*)d_in[1];
    const float* Mu0 = (const float*)d_in[2];
    const float* Mu1 = (const float*)d_in[3];
    const float* S0  = (const float*)d_in[4];
    const float* S1  = (const float*)d_in[5];
    const float* Lam = (const float*)d_in[6];
    float* out = (float*)d_out;

    // 3 launches/sequence: ncu captures 0-based launch index 3
    // (confirmed R2/R3/R9/R15) = second sequence's gmm_main -> profile it.
    gmm_main<<<MAIN_CTAS, 256>>>(X, t, Mu0, Mu1, S0, S1, Lam);
    gmm_red1<<<dim3(NB, 4), 256>>>();
    gmm_red2<<<NB, 64>>>(out);
}